// round 6
// baseline (speedup 1.0000x reference)
#include <cuda_runtime.h>
#include <cuda_bf16.h>
#include <cstdint>

// ============================================================================
// Problem dims (fixed by the dataset)
// ============================================================================
#define N_TOK   4096      // B*S = 2*2048
#define V_DIM   32000
#define K_DIM   1024
#define EPSF    1e-5f
#define K0_CONST 12.8992199f   // ln(4/eps) = ln(400000)

// GEMM tiling — FP8 e4m3 mma.sync m16n8k32 (same MAC rate as bf16 on the
// legacy pipe, but HALF the smem bytes per MAC — we are smem-crossbar bound).
// R4 structure: grid (32,250), 2 CTAs/SM, 3-stage cp.async ring.
#define BM      128
#define BN      128
#define BK      128                // fp8 elems per K-chunk = 128 bytes/row
#define KITERS  (K_DIM / BK)       // 8
#define STAGES  3
#define THREADS 256

#define A_BYTES     (BM * BK)                // 16384
#define B_BYTES     (BN * BK)                // 16384
#define STAGE_BYTES (A_BYTES + B_BYTES)      // 32768
#define TABLE_BYTES ((BM + BN) * 2 * 4)      // 2048
#define SMEM_DYN    (128 + STAGES * STAGE_BYTES + TABLE_BYTES)   // ~100.5 KB

// Operands pre-scaled by 16 each -> MMA result = 256 * (xhat . yhat)
#define INV_GSCALE 0.00390625f     // 1/256

// ============================================================================
// Device-global scratch (allocation-free rule: __device__ arrays)
// ============================================================================
__device__ __align__(128) uint8_t g_xb[(size_t)N_TOK * K_DIM];   //  4 MB e4m3
__device__ __align__(128) uint8_t g_yb[(size_t)V_DIM * K_DIM];   // 32 MB e4m3
__device__ float g_xsq[N_TOK];
__device__ float g_Ax[N_TOK];     // (1 - xsq) * 1e5
__device__ float g_ysq[V_DIM];
__device__ float g_By[V_DIM];     // (1 - ysq)

// ============================================================================
// PTX helpers (base-target only: cp.async, ldmatrix, mma.sync fp8)
// ============================================================================
__device__ __forceinline__ uint32_t smem_u32(const void* p) {
    uint32_t a;
    asm("{ .reg .u64 t; cvta.to.shared.u64 t, %1; cvt.u32.u64 %0, t; }"
        : "=r"(a) : "l"(p));
    return a;
}

#define CP_ASYNC16(saddr, gptr) \
    asm volatile("cp.async.cg.shared.global [%0], [%1], 16;" \
                 :: "r"(saddr), "l"(gptr) : "memory")
#define CP_COMMIT() asm volatile("cp.async.commit_group;" ::: "memory")
#define CP_WAIT1()  asm volatile("cp.async.wait_group 1;" ::: "memory")

#define LDSM4(r0, r1, r2, r3, addr) \
    asm volatile("ldmatrix.sync.aligned.m8n8.x4.shared.b16 {%0,%1,%2,%3}, [%4];" \
                 : "=r"(r0), "=r"(r1), "=r"(r2), "=r"(r3) : "r"(addr))

// e4m3 x e4m3 -> f32, m16n8k32 (4096 MACs / warp instruction)
#define MMA16832(c, a, b0, b1) \
    asm volatile("mma.sync.aligned.m16n8k32.row.col.f32.e4m3.e4m3.f32 " \
                 "{%0,%1,%2,%3}, {%4,%5,%6,%7}, {%8,%9}, {%0,%1,%2,%3};" \
                 : "+f"((c)[0]), "+f"((c)[1]), "+f"((c)[2]), "+f"((c)[3]) \
                 : "r"((a)[0]), "r"((a)[1]), "r"((a)[2]), "r"((a)[3]), \
                   "r"(b0), "r"(b1))

// pack two floats -> e4m3x2 (lo byte = first arg's lo)
__device__ __forceinline__ uint16_t f2e4m3x2(float lo, float hi) {
    uint16_t r;
    asm("cvt.rn.satfinite.e4m3x2.f32 %0, %1, %2;" : "=h"(r) : "f"(hi), "f"(lo));
    return r;
}

// ============================================================================
// Prep kernel: Poincare projection -> e4m3 operands (x16) + per-row scalars
// ============================================================================
__global__ void __launch_bounds__(256) prep_kernel(const float* __restrict__ src,
                                                   int which) {
    const int row = blockIdx.x;
    const int tid = threadIdx.x;

    const float4 v = reinterpret_cast<const float4*>(src)[(size_t)row * 256 + tid];
    float ss = fmaf(v.x, v.x, fmaf(v.y, v.y, fmaf(v.z, v.z, v.w * v.w)));
    #pragma unroll
    for (int o = 16; o; o >>= 1) ss += __shfl_xor_sync(0xFFFFFFFFu, ss, o);

    __shared__ float wsum[8];
    if ((tid & 31) == 0) wsum[tid >> 5] = ss;
    __syncthreads();
    float total = 0.f;
    #pragma unroll
    for (int i = 0; i < 8; ++i) total += wsum[i];

    const float norm  = sqrtf(total);
    const float scale = fminf((1.0f - EPSF) / (norm + 1e-10f), 1.0f);
    const float sq    = scale * scale * total;

    uint8_t* dst = (which == 0) ? g_xb : g_yb;
    if (tid == 0) {
        if (which == 0) { g_xsq[row] = sq; g_Ax[row] = (1.0f - sq) * 1e5f; }
        else            { g_ysq[row] = sq; g_By[row] = (1.0f - sq); }
    }

    // extra 16x so e4m3 sees sigma ~0.5; exact /256 undone on the dot product
    const float s16 = scale * 16.0f;
    const uint32_t lo = f2e4m3x2(v.x * s16, v.y * s16);
    const uint32_t hi = f2e4m3x2(v.z * s16, v.w * s16);
    reinterpret_cast<uint32_t*>(dst)[(size_t)row * 256 + tid] = lo | (hi << 16);
}

// ============================================================================
// Hyperbolic epilogue transform (fast closed form; guarded exact path).
// g is the raw MMA dot (scaled by 256).
// ============================================================================
__device__ __forceinline__ float hyp(float g, float xs, float An,
                                     float ys, float By) {
    const float d2 = fmaf(-2.0f * INV_GSCALE, g, xs + ys);
    const float ab = An * By;       // (1-xs)(1-ys)/eps
    if (d2 > 0.25f && ab < 0.01f) {
        // -acosh(1 + 2*sqrt(d2)/(denom+eps)) ~= ab - ln(4/eps) - 0.5*ln(d2)
        return fmaf(-0.5f, __logf(d2), ab - K0_CONST);
    }
    const float dist  = sqrtf(fmaxf(d2, 0.0f));
    const float denom = (An * EPSF) * By + EPSF;
    const float arg   = fmaxf(1.0f + 2.0f * dist / denom, 1.0f + EPSF);
    return -acoshf(arg);
}

// ============================================================================
// Fused GEMM + epilogue.  grid (32, 250), 256 threads, 2 CTAs/SM.
// Warp grid 2(M) x 4(N); warp tile 64x32; 64 fp32 accums / thread.
// SMEM: 3-stage cp.async pipeline, 128B rows, chunk^=(row&7) swizzle.
// ============================================================================
__device__ __forceinline__ void issue_stage(uint32_t tiles, int s, int kt,
                                            const char* gA, const char* gB,
                                            int tid) {
    const uint32_t aSt = tiles + (uint32_t)s * STAGE_BYTES;
    const uint32_t bSt = aSt + A_BYTES;
    const size_t kOff = (size_t)kt * BK;          // 128 bytes into the row
    #pragma unroll
    for (int t = 0; t < 4; ++t) {                 // A: 128 rows x 8 chunks
        const int idx = t * THREADS + tid;
        const int row = idx >> 3, ch = idx & 7;
        const char* gp = gA + (size_t)row * K_DIM + kOff + (size_t)ch * 16;
        const uint32_t sa = aSt + (uint32_t)(row * 128 + ((ch ^ (row & 7)) * 16));
        CP_ASYNC16(sa, gp);
    }
    #pragma unroll
    for (int t = 0; t < 4; ++t) {                 // B: 128 rows x 8 chunks
        const int idx = t * THREADS + tid;
        const int row = idx >> 3, ch = idx & 7;
        const char* gp = gB + (size_t)row * K_DIM + kOff + (size_t)ch * 16;
        const uint32_t sa = bSt + (uint32_t)(row * 128 + ((ch ^ (row & 7)) * 16));
        CP_ASYNC16(sa, gp);
    }
}

__global__ void __launch_bounds__(THREADS, 2) hyper_gemm(float* __restrict__ out) {
    extern __shared__ char smem[];
    const uint32_t sb    = smem_u32(smem);
    const uint32_t tiles = (sb + 127) & ~127u;
    char* smemc = smem + (tiles - sb);

    float* sXs  = reinterpret_cast<float*>(smemc + STAGES * STAGE_BYTES);
    float* sAn  = sXs + BM;
    float* sYsq = sAn + BM;
    float* sBy  = sYsq + BN;

    const int tid  = threadIdx.x;
    const int lane = tid & 31;
    const int wid  = tid >> 5;
    const int wm   = wid >> 2;          // 0..1  (M direction, 64 rows each)
    const int wn   = wid & 3;           // 0..3  (N direction, 32 cols each)
    const int m0   = blockIdx.x * BM;
    const int v0   = blockIdx.y * BN;

    // epilogue tables
    if (tid < BM) { sXs[tid] = g_xsq[m0 + tid]; sAn[tid] = g_Ax[m0 + tid]; }
    else { const int c = tid - BM; sYsq[c] = g_ysq[v0 + c]; sBy[c] = g_By[v0 + c]; }

    const char* gA = reinterpret_cast<const char*>(g_xb) + (size_t)m0 * K_DIM;
    const char* gB = reinterpret_cast<const char*>(g_yb) + (size_t)v0 * K_DIM;

    // prologue: fill 2 stages
    issue_stage(tiles, 0, 0, gA, gB, tid); CP_COMMIT();
    issue_stage(tiles, 1, 1, gA, gB, tid); CP_COMMIT();

    float acc[4][4][4] = {};

    // per-thread ldmatrix address components (16B chunks; a k32 step uses the
    // chunk pair (2kk, 2kk+1) — byte-identical structure to the bf16 layout)
    const int aRowB = wm * 64 + (lane & 15);                        // + i*16
    const int aChB  = lane >> 4;                                    // + 2*kk
    const int bRowB = wn * 32 + (lane & 7) + ((lane >> 4) << 3);    // + jp*16
    const int bChB  = (lane >> 3) & 1;                              // + 2*kk
    const int swz   = lane & 7;

    #pragma unroll 1
    for (int kt = 0; kt < KITERS; ++kt) {
        CP_WAIT1();              // stage kt has landed (<=1 group outstanding)
        __syncthreads();         // all warps done reading stage kt-1
        if (kt + 2 < KITERS)
            issue_stage(tiles, (kt + 2) % 3, kt + 2, gA, gB, tid);
        CP_COMMIT();             // commit every iter (possibly empty group)

        const int s = kt % 3;
        const uint32_t aSt = tiles + (uint32_t)s * STAGE_BYTES;
        const uint32_t bSt = aSt + A_BYTES;

        #pragma unroll
        for (int kk = 0; kk < 4; ++kk) {         // 4 x k32 per 128-elt chunk
            uint32_t af[4][4];
            #pragma unroll
            for (int i = 0; i < 4; ++i) {
                const uint32_t addr = aSt
                    + (uint32_t)((aRowB + i * 16) * 128)
                    + (uint32_t)((((kk * 2 + aChB) ^ swz) * 16));
                LDSM4(af[i][0], af[i][1], af[i][2], af[i][3], addr);
            }
            uint32_t bf[2][4];   // jp -> frags for n-subtiles 2jp, 2jp+1
            #pragma unroll
            for (int jp = 0; jp < 2; ++jp) {
                const uint32_t addr = bSt
                    + (uint32_t)((bRowB + jp * 16) * 128)
                    + (uint32_t)((((kk * 2 + bChB) ^ swz) * 16));
                LDSM4(bf[jp][0], bf[jp][1], bf[jp][2], bf[jp][3], addr);
            }
            #pragma unroll
            for (int i = 0; i < 4; ++i)
                #pragma unroll
                for (int j = 0; j < 4; ++j)
                    MMA16832(acc[i][j], af[i],
                             bf[j >> 1][(j & 1) * 2],
                             bf[j >> 1][(j & 1) * 2 + 1]);
        }
    }

    // ---------------- epilogue: transform + store ----------------
    const int rBase = wm * 64 + (lane >> 2);        // + i*16 (+8)
    const int cBase = wn * 32 + (lane & 3) * 2;     // + j*8

    #pragma unroll
    for (int i = 0; i < 4; ++i) {
        const int ra = rBase + i * 16;
        const int rb = ra + 8;
        const float xsa = sXs[ra], Ana = sAn[ra];
        const float xsb = sXs[rb], Anb = sAn[rb];
        float* outA = out + (size_t)(m0 + ra) * V_DIM + v0;
        float* outB = out + (size_t)(m0 + rb) * V_DIM + v0;
        #pragma unroll
        for (int j = 0; j < 4; ++j) {
            const int lc = cBase + j * 8;
            const float ys0 = sYsq[lc],     By0 = sBy[lc];
            const float ys1 = sYsq[lc + 1], By1 = sBy[lc + 1];
            float2 pa, pb;
            pa.x = hyp(acc[i][j][0], xsa, Ana, ys0, By0);
            pa.y = hyp(acc[i][j][1], xsa, Ana, ys1, By1);
            pb.x = hyp(acc[i][j][2], xsb, Anb, ys0, By0);
            pb.y = hyp(acc[i][j][3], xsb, Anb, ys1, By1);
            *reinterpret_cast<float2*>(outA + lc) = pa;
            *reinterpret_cast<float2*>(outB + lc) = pb;
        }
    }
}

// ============================================================================
// Launch
// ============================================================================
extern "C" void kernel_launch(void* const* d_in, const int* in_sizes, int n_in,
                              void* d_out, int out_size) {
    const float* hidden = (const float*)d_in[0];
    const float* weight = (const float*)d_in[1];
    float* out = (float*)d_out;

    prep_kernel<<<N_TOK, 256>>>(hidden, 0);
    prep_kernel<<<V_DIM, 256>>>(weight, 1);

    cudaFuncSetAttribute(hyper_gemm,
                         cudaFuncAttributeMaxDynamicSharedMemorySize, SMEM_DYN);
    dim3 grid(N_TOK / BM, V_DIM / BN);   // m-fastest: A L2-resident, B streamed once
    hyper_gemm<<<grid, THREADS, SMEM_DYN>>>(out);
}

// round 7
// speedup vs baseline: 1.2157x; 1.2157x over previous
#include <cuda_runtime.h>
#include <cuda_bf16.h>
#include <cstdint>

// ============================================================================
// Problem dims (fixed by the dataset)
// ============================================================================
#define N_TOK   4096      // B*S = 2*2048
#define V_DIM   32000
#define K_DIM   1024
#define EPSF    1e-5f
#define K0_CONST 12.8992199f   // ln(4/eps) = ln(400000)

// GEMM tiling — bf16 mma.sync m16n8k16 legacy pipe (proven R4 config):
// grid (32,250), 2 CTAs/SM, 3-stage cp.async ring, warp tile 64x32.
#define BM      128
#define BN      128
#define BK      64                 // bf16 per K-chunk = 128 bytes/row
#define KITERS  (K_DIM / BK)       // 16
#define STAGES  3
#define THREADS 256

#define A_BYTES     (BM * BK * 2)            // 16384
#define B_BYTES     (BN * BK * 2)            // 16384
#define STAGE_BYTES (A_BYTES + B_BYTES)      // 32768
#define TABLE_BYTES ((BM + BN) * 2 * 4)      // 2048
#define SMEM_DYN    (128 + STAGES * STAGE_BYTES + TABLE_BYTES)   // ~100.5 KB

// prep: 8 rows per 256-thread block (one warp per row)
#define PREP_ROWS_TOT (N_TOK + V_DIM)        // 36096
#define PREP_GRID     (PREP_ROWS_TOT / 8)    // 4512

// ============================================================================
// Device-global scratch (allocation-free rule: __device__ arrays)
// ============================================================================
__device__ __align__(128) __nv_bfloat16 g_xb[(size_t)N_TOK * K_DIM];   //  8 MB
__device__ __align__(128) __nv_bfloat16 g_yb[(size_t)V_DIM * K_DIM];   // 64 MB
__device__ float g_xsq[N_TOK];
__device__ float g_Ax[N_TOK];     // (1 - xsq) * 1e5
__device__ float g_ysq[V_DIM];
__device__ float g_By[V_DIM];     // (1 - ysq)

// ============================================================================
// PTX helpers (base-target only: cp.async, ldmatrix, mma.sync)
// ============================================================================
__device__ __forceinline__ uint32_t smem_u32(const void* p) {
    uint32_t a;
    asm("{ .reg .u64 t; cvta.to.shared.u64 t, %1; cvt.u32.u64 %0, t; }"
        : "=r"(a) : "l"(p));
    return a;
}

#define CP_ASYNC16(saddr, gptr) \
    asm volatile("cp.async.cg.shared.global [%0], [%1], 16;" \
                 :: "r"(saddr), "l"(gptr) : "memory")
#define CP_COMMIT() asm volatile("cp.async.commit_group;" ::: "memory")
#define CP_WAIT1()  asm volatile("cp.async.wait_group 1;" ::: "memory")

#define LDSM4(r0, r1, r2, r3, addr) \
    asm volatile("ldmatrix.sync.aligned.m8n8.x4.shared.b16 {%0,%1,%2,%3}, [%4];" \
                 : "=r"(r0), "=r"(r1), "=r"(r2), "=r"(r3) : "r"(addr))

#define MMA16816(c, a, b0, b1) \
    asm volatile("mma.sync.aligned.m16n8k16.row.col.f32.bf16.bf16.f32 " \
                 "{%0,%1,%2,%3}, {%4,%5,%6,%7}, {%8,%9}, {%0,%1,%2,%3};" \
                 : "+f"((c)[0]), "+f"((c)[1]), "+f"((c)[2]), "+f"((c)[3]) \
                 : "r"((a)[0]), "r"((a)[1]), "r"((a)[2]), "r"((a)[3]), \
                   "r"(b0), "r"(b1))

// ============================================================================
// Fused prep kernel: one warp per row, 8 rows per block, both tensors.
// Lane-strided float4 loads (coalesced, MLP=8), shuffle-only reduction.
// row < N_TOK -> hidden -> g_xb/g_xsq/g_Ax ; else weight -> g_yb/g_ysq/g_By
// ============================================================================
__global__ void __launch_bounds__(256) prep_all(const float* __restrict__ hidden,
                                                const float* __restrict__ weight) {
    const int lane = threadIdx.x & 31;
    const int w    = threadIdx.x >> 5;
    const int row  = blockIdx.x * 8 + w;

    const bool isx = (row < N_TOK);
    const int  r   = isx ? row : row - N_TOK;
    const float4* src = reinterpret_cast<const float4*>(isx ? hidden : weight)
                        + (size_t)r * 256;

    // load 8 float4 per lane, lane-strided for coalescing
    float4 v[8];
    #pragma unroll
    for (int j = 0; j < 8; ++j) v[j] = src[j * 32 + lane];

    float ss = 0.f;
    #pragma unroll
    for (int j = 0; j < 8; ++j)
        ss += fmaf(v[j].x, v[j].x, fmaf(v[j].y, v[j].y,
              fmaf(v[j].z, v[j].z, v[j].w * v[j].w)));
    #pragma unroll
    for (int o = 16; o; o >>= 1) ss += __shfl_xor_sync(0xFFFFFFFFu, ss, o);

    const float norm  = sqrtf(ss);
    const float scale = fminf((1.0f - EPSF) / (norm + 1e-10f), 1.0f);
    const float sq    = scale * scale * ss;

    if (lane == 0) {
        if (isx) { g_xsq[r] = sq; g_Ax[r] = (1.0f - sq) * 1e5f; }
        else     { g_ysq[r] = sq; g_By[r] = (1.0f - sq); }
    }

    uint2* dst = reinterpret_cast<uint2*>(isx ? g_xb : g_yb) + (size_t)r * 256;
    #pragma unroll
    for (int j = 0; j < 8; ++j) {
        __nv_bfloat162 b0 = __float22bfloat162_rn(
            make_float2(v[j].x * scale, v[j].y * scale));
        __nv_bfloat162 b1 = __float22bfloat162_rn(
            make_float2(v[j].z * scale, v[j].w * scale));
        uint2 u;
        u.x = *reinterpret_cast<uint32_t*>(&b0);
        u.y = *reinterpret_cast<uint32_t*>(&b1);
        dst[j * 32 + lane] = u;
    }
}

// ============================================================================
// Hyperbolic epilogue transform (fast closed form; guarded exact path)
// ============================================================================
__device__ __forceinline__ float hyp(float g, float xs, float An,
                                     float ys, float By) {
    const float d2 = fmaf(-2.0f, g, xs + ys);
    const float ab = An * By;       // (1-xs)(1-ys)/eps
    if (d2 > 0.25f && ab < 0.01f) {
        // -acosh(1 + 2*sqrt(d2)/(denom+eps)) ~= ab - ln(4/eps) - 0.5*ln(d2)
        return fmaf(-0.5f, __logf(d2), ab - K0_CONST);
    }
    const float dist  = sqrtf(fmaxf(d2, 0.0f));
    const float denom = (An * EPSF) * By + EPSF;
    const float arg   = fmaxf(1.0f + 2.0f * dist / denom, 1.0f + EPSF);
    return -acoshf(arg);
}

// ============================================================================
// Fused GEMM + epilogue (R4, unchanged).  grid (32, 250), 2 CTAs/SM.
// ============================================================================
__device__ __forceinline__ void issue_stage(uint32_t tiles, int s, int kt,
                                            const char* gA, const char* gB,
                                            int tid) {
    const uint32_t aSt = tiles + (uint32_t)s * STAGE_BYTES;
    const uint32_t bSt = aSt + A_BYTES;
    const size_t kOff = (size_t)kt * (BK * 2);    // 128 bytes into the row
    #pragma unroll
    for (int t = 0; t < 4; ++t) {                 // A: 128 rows x 8 chunks
        const int idx = t * THREADS + tid;
        const int row = idx >> 3, ch = idx & 7;
        const char* gp = gA + (size_t)row * (K_DIM * 2) + kOff + (size_t)ch * 16;
        const uint32_t sa = aSt + (uint32_t)(row * 128 + ((ch ^ (row & 7)) * 16));
        CP_ASYNC16(sa, gp);
    }
    #pragma unroll
    for (int t = 0; t < 4; ++t) {                 // B: 128 rows x 8 chunks
        const int idx = t * THREADS + tid;
        const int row = idx >> 3, ch = idx & 7;
        const char* gp = gB + (size_t)row * (K_DIM * 2) + kOff + (size_t)ch * 16;
        const uint32_t sa = bSt + (uint32_t)(row * 128 + ((ch ^ (row & 7)) * 16));
        CP_ASYNC16(sa, gp);
    }
}

__global__ void __launch_bounds__(THREADS, 2) hyper_gemm(float* __restrict__ out) {
    extern __shared__ char smem[];
    const uint32_t sb    = smem_u32(smem);
    const uint32_t tiles = (sb + 127) & ~127u;
    char* smemc = smem + (tiles - sb);

    float* sXs  = reinterpret_cast<float*>(smemc + STAGES * STAGE_BYTES);
    float* sAn  = sXs + BM;
    float* sYsq = sAn + BM;
    float* sBy  = sYsq + BN;

    const int tid  = threadIdx.x;
    const int lane = tid & 31;
    const int wid  = tid >> 5;
    const int wm   = wid >> 2;          // 0..1  (M direction, 64 rows each)
    const int wn   = wid & 3;           // 0..3  (N direction, 32 cols each)
    const int m0   = blockIdx.x * BM;
    const int v0   = blockIdx.y * BN;

    // epilogue tables
    if (tid < BM) { sXs[tid] = g_xsq[m0 + tid]; sAn[tid] = g_Ax[m0 + tid]; }
    else { const int c = tid - BM; sYsq[c] = g_ysq[v0 + c]; sBy[c] = g_By[v0 + c]; }

    const char* gA = reinterpret_cast<const char*>(g_xb) + (size_t)m0 * (K_DIM * 2);
    const char* gB = reinterpret_cast<const char*>(g_yb) + (size_t)v0 * (K_DIM * 2);

    // prologue: fill 2 stages
    issue_stage(tiles, 0, 0, gA, gB, tid); CP_COMMIT();
    issue_stage(tiles, 1, 1, gA, gB, tid); CP_COMMIT();

    float acc[4][4][4] = {};

    // per-thread ldmatrix address components
    const int aRowB = wm * 64 + (lane & 15);                        // + i*16
    const int aChB  = lane >> 4;                                    // + 2*kk
    const int bRowB = wn * 32 + (lane & 7) + ((lane >> 4) << 3);    // + jp*16
    const int bChB  = (lane >> 3) & 1;                              // + 2*kk
    const int swz   = lane & 7;

    #pragma unroll 1
    for (int kt = 0; kt < KITERS; ++kt) {
        CP_WAIT1();              // stage kt has landed (<=1 group outstanding)
        __syncthreads();         // all warps done reading stage kt-1
        if (kt + 2 < KITERS)
            issue_stage(tiles, (kt + 2) % 3, kt + 2, gA, gB, tid);
        CP_COMMIT();             // commit every iter (possibly empty group)

        const int s = kt % 3;
        const uint32_t aSt = tiles + (uint32_t)s * STAGE_BYTES;
        const uint32_t bSt = aSt + A_BYTES;

        #pragma unroll
        for (int kk = 0; kk < 4; ++kk) {         // 4 x k16 per 64-elt chunk
            uint32_t af[4][4];
            #pragma unroll
            for (int i = 0; i < 4; ++i) {
                const uint32_t addr = aSt
                    + (uint32_t)((aRowB + i * 16) * 128)
                    + (uint32_t)((((kk * 2 + aChB) ^ swz) * 16));
                LDSM4(af[i][0], af[i][1], af[i][2], af[i][3], addr);
            }
            uint32_t bf[2][4];
            #pragma unroll
            for (int jp = 0; jp < 2; ++jp) {
                const uint32_t addr = bSt
                    + (uint32_t)((bRowB + jp * 16) * 128)
                    + (uint32_t)((((kk * 2 + bChB) ^ swz) * 16));
                LDSM4(bf[jp][0], bf[jp][1], bf[jp][2], bf[jp][3], addr);
            }
            #pragma unroll
            for (int i = 0; i < 4; ++i)
                #pragma unroll
                for (int j = 0; j < 4; ++j)
                    MMA16816(acc[i][j], af[i],
                             bf[j >> 1][(j & 1) * 2],
                             bf[j >> 1][(j & 1) * 2 + 1]);
        }
    }

    // ---------------- epilogue: transform + store ----------------
    const int rBase = wm * 64 + (lane >> 2);        // + i*16 (+8)
    const int cBase = wn * 32 + (lane & 3) * 2;     // + j*8

    #pragma unroll
    for (int i = 0; i < 4; ++i) {
        const int ra = rBase + i * 16;
        const int rb = ra + 8;
        const float xsa = sXs[ra], Ana = sAn[ra];
        const float xsb = sXs[rb], Anb = sAn[rb];
        float* outA = out + (size_t)(m0 + ra) * V_DIM + v0;
        float* outB = out + (size_t)(m0 + rb) * V_DIM + v0;
        #pragma unroll
        for (int j = 0; j < 4; ++j) {
            const int lc = cBase + j * 8;
            const float ys0 = sYsq[lc],     By0 = sBy[lc];
            const float ys1 = sYsq[lc + 1], By1 = sBy[lc + 1];
            float2 pa, pb;
            pa.x = hyp(acc[i][j][0], xsa, Ana, ys0, By0);
            pa.y = hyp(acc[i][j][1], xsa, Ana, ys1, By1);
            pb.x = hyp(acc[i][j][2], xsb, Anb, ys0, By0);
            pb.y = hyp(acc[i][j][3], xsb, Anb, ys1, By1);
            *reinterpret_cast<float2*>(outA + lc) = pa;
            *reinterpret_cast<float2*>(outB + lc) = pb;
        }
    }
}

// ============================================================================
// Launch
// ============================================================================
extern "C" void kernel_launch(void* const* d_in, const int* in_sizes, int n_in,
                              void* d_out, int out_size) {
    const float* hidden = (const float*)d_in[0];
    const float* weight = (const float*)d_in[1];
    float* out = (float*)d_out;

    prep_all<<<PREP_GRID, 256>>>(hidden, weight);

    cudaFuncSetAttribute(hyper_gemm,
                         cudaFuncAttributeMaxDynamicSharedMemorySize, SMEM_DYN);
    dim3 grid(N_TOK / BM, V_DIM / BN);   // m-fastest: A L2-resident, B streamed once
    hyper_gemm<<<grid, THREADS, SMEM_DYN>>>(out);
}

// round 8
// speedup vs baseline: 1.2179x; 1.0018x over previous
#include <cuda_runtime.h>
#include <cuda_bf16.h>
#include <cstdint>

// ============================================================================
// Problem dims (fixed by the dataset)
// ============================================================================
#define N_TOK   4096      // B*S = 2*2048
#define V_DIM   32000
#define K_DIM   1024
#define EPSF    1e-5f
#define K0_CONST 12.8992199f   // ln(4/eps) = ln(400000)

// GEMM tiling — bf16 mma.sync m16n8k16 legacy pipe (proven R4 config):
// grid (32,250), 2 CTAs/SM, 3-stage cp.async ring, warp tile 64x32.
#define BM      128
#define BN      128
#define BK      64                 // bf16 per K-chunk = 128 bytes/row
#define KITERS  (K_DIM / BK)       // 16
#define STAGES  3
#define THREADS 256

#define A_BYTES     (BM * BK * 2)            // 16384
#define B_BYTES     (BN * BK * 2)            // 16384
#define STAGE_BYTES (A_BYTES + B_BYTES)      // 32768
#define TABLE_BYTES ((BM + BN) * 2 * 4)      // 2048
#define SMEM_DYN    (128 + STAGES * STAGE_BYTES + TABLE_BYTES)   // ~100.5 KB

// prep: 8 rows per 256-thread block (one warp per row)
#define PREP_ROWS_TOT (N_TOK + V_DIM)        // 36096
#define PREP_GRID     (PREP_ROWS_TOT / 8)    // 4512

// ============================================================================
// Device-global scratch (allocation-free rule: __device__ arrays)
// ============================================================================
__device__ __align__(128) __nv_bfloat16 g_xb[(size_t)N_TOK * K_DIM];   //  8 MB
__device__ __align__(128) __nv_bfloat16 g_yb[(size_t)V_DIM * K_DIM];   // 64 MB
__device__ float g_xsq[N_TOK];
__device__ float g_Ax[N_TOK];     // (1 - xsq) * 1e5
__device__ float g_ysq[V_DIM];
__device__ float g_By[V_DIM];     // (1 - ysq)

// ============================================================================
// PTX helpers (base-target only: cp.async, ldmatrix, mma.sync)
// ============================================================================
__device__ __forceinline__ uint32_t smem_u32(const void* p) {
    uint32_t a;
    asm("{ .reg .u64 t; cvta.to.shared.u64 t, %1; cvt.u32.u64 %0, t; }"
        : "=r"(a) : "l"(p));
    return a;
}

#define CP_ASYNC16(saddr, gptr) \
    asm volatile("cp.async.cg.shared.global [%0], [%1], 16;" \
                 :: "r"(saddr), "l"(gptr) : "memory")
#define CP_COMMIT() asm volatile("cp.async.commit_group;" ::: "memory")
#define CP_WAIT1()  asm volatile("cp.async.wait_group 1;" ::: "memory")

#define LDSM4(r0, r1, r2, r3, addr) \
    asm volatile("ldmatrix.sync.aligned.m8n8.x4.shared.b16 {%0,%1,%2,%3}, [%4];" \
                 : "=r"(r0), "=r"(r1), "=r"(r2), "=r"(r3) : "r"(addr))

#define MMA16816(c, a, b0, b1) \
    asm volatile("mma.sync.aligned.m16n8k16.row.col.f32.bf16.bf16.f32 " \
                 "{%0,%1,%2,%3}, {%4,%5,%6,%7}, {%8,%9}, {%0,%1,%2,%3};" \
                 : "+f"((c)[0]), "+f"((c)[1]), "+f"((c)[2]), "+f"((c)[3]) \
                 : "r"((a)[0]), "r"((a)[1]), "r"((a)[2]), "r"((a)[3]), \
                   "r"(b0), "r"(b1))

// ============================================================================
// Fused prep kernel: one warp per row, 8 rows per block, both tensors.
// ============================================================================
__global__ void __launch_bounds__(256) prep_all(const float* __restrict__ hidden,
                                                const float* __restrict__ weight) {
    const int lane = threadIdx.x & 31;
    const int w    = threadIdx.x >> 5;
    const int row  = blockIdx.x * 8 + w;

    const bool isx = (row < N_TOK);
    const int  r   = isx ? row : row - N_TOK;
    const float4* src = reinterpret_cast<const float4*>(isx ? hidden : weight)
                        + (size_t)r * 256;

    float4 v[8];
    #pragma unroll
    for (int j = 0; j < 8; ++j) v[j] = src[j * 32 + lane];

    float ss = 0.f;
    #pragma unroll
    for (int j = 0; j < 8; ++j)
        ss += fmaf(v[j].x, v[j].x, fmaf(v[j].y, v[j].y,
              fmaf(v[j].z, v[j].z, v[j].w * v[j].w)));
    #pragma unroll
    for (int o = 16; o; o >>= 1) ss += __shfl_xor_sync(0xFFFFFFFFu, ss, o);

    const float norm  = sqrtf(ss);
    const float scale = fminf((1.0f - EPSF) / (norm + 1e-10f), 1.0f);
    const float sq    = scale * scale * ss;

    if (lane == 0) {
        if (isx) { g_xsq[r] = sq; g_Ax[r] = (1.0f - sq) * 1e5f; }
        else     { g_ysq[r] = sq; g_By[r] = (1.0f - sq); }
    }

    uint2* dst = reinterpret_cast<uint2*>(isx ? g_xb : g_yb) + (size_t)r * 256;
    #pragma unroll
    for (int j = 0; j < 8; ++j) {
        __nv_bfloat162 b0 = __float22bfloat162_rn(
            make_float2(v[j].x * scale, v[j].y * scale));
        __nv_bfloat162 b1 = __float22bfloat162_rn(
            make_float2(v[j].z * scale, v[j].w * scale));
        uint2 u;
        u.x = *reinterpret_cast<uint32_t*>(&b0);
        u.y = *reinterpret_cast<uint32_t*>(&b1);
        dst[j * 32 + lane] = u;
    }
}

// ============================================================================
// Hyperbolic epilogue transform (fast closed form; guarded exact path)
// ============================================================================
__device__ __forceinline__ float hyp(float g, float xs, float An,
                                     float ys, float By) {
    const float d2 = fmaf(-2.0f, g, xs + ys);
    const float ab = An * By;       // (1-xs)(1-ys)/eps
    if (d2 > 0.25f && ab < 0.01f) {
        // -acosh(1 + 2*sqrt(d2)/(denom+eps)) ~= ab - ln(4/eps) - 0.5*ln(d2)
        return fmaf(-0.5f, __logf(d2), ab - K0_CONST);
    }
    const float dist  = sqrtf(fmaxf(d2, 0.0f));
    const float denom = (An * EPSF) * By + EPSF;
    const float arg   = fmaxf(1.0f + 2.0f * dist / denom, 1.0f + EPSF);
    return -acoshf(arg);
}

// ============================================================================
// Fused GEMM + epilogue.  grid (32, 250), 2 CTAs/SM, 256 threads.
// Inner loop restructured: A-fragment double-buffer (frees 8 regs, explicit
// LDSM->MMA skew) + warp-parity kk stagger (anti-phases LDSM/MMA bursts
// across warps so tensor and L1 pipes run concurrently).
// ============================================================================
__device__ __forceinline__ void issue_stage(uint32_t tiles, int s, int kt,
                                            const char* gA, const char* gB,
                                            int tid) {
    const uint32_t aSt = tiles + (uint32_t)s * STAGE_BYTES;
    const uint32_t bSt = aSt + A_BYTES;
    const size_t kOff = (size_t)kt * (BK * 2);    // 128 bytes into the row
    #pragma unroll
    for (int t = 0; t < 4; ++t) {                 // A: 128 rows x 8 chunks
        const int idx = t * THREADS + tid;
        const int row = idx >> 3, ch = idx & 7;
        const char* gp = gA + (size_t)row * (K_DIM * 2) + kOff + (size_t)ch * 16;
        const uint32_t sa = aSt + (uint32_t)(row * 128 + ((ch ^ (row & 7)) * 16));
        CP_ASYNC16(sa, gp);
    }
    #pragma unroll
    for (int t = 0; t < 4; ++t) {                 // B: 128 rows x 8 chunks
        const int idx = t * THREADS + tid;
        const int row = idx >> 3, ch = idx & 7;
        const char* gp = gB + (size_t)row * (K_DIM * 2) + kOff + (size_t)ch * 16;
        const uint32_t sa = bSt + (uint32_t)(row * 128 + ((ch ^ (row & 7)) * 16));
        CP_ASYNC16(sa, gp);
    }
}

__global__ void __launch_bounds__(THREADS, 2) hyper_gemm(float* __restrict__ out) {
    extern __shared__ char smem[];
    const uint32_t sb    = smem_u32(smem);
    const uint32_t tiles = (sb + 127) & ~127u;
    char* smemc = smem + (tiles - sb);

    float* sXs  = reinterpret_cast<float*>(smemc + STAGES * STAGE_BYTES);
    float* sAn  = sXs + BM;
    float* sYsq = sAn + BM;
    float* sBy  = sYsq + BN;

    const int tid  = threadIdx.x;
    const int lane = tid & 31;
    const int wid  = tid >> 5;
    const int wm   = wid >> 2;          // 0..1  (M direction, 64 rows each)
    const int wn   = wid & 3;           // 0..3  (N direction, 32 cols each)
    const int m0   = blockIdx.x * BM;
    const int v0   = blockIdx.y * BN;

    // epilogue tables
    if (tid < BM) { sXs[tid] = g_xsq[m0 + tid]; sAn[tid] = g_Ax[m0 + tid]; }
    else { const int c = tid - BM; sYsq[c] = g_ysq[v0 + c]; sBy[c] = g_By[v0 + c]; }

    const char* gA = reinterpret_cast<const char*>(g_xb) + (size_t)m0 * (K_DIM * 2);
    const char* gB = reinterpret_cast<const char*>(g_yb) + (size_t)v0 * (K_DIM * 2);

    // prologue: fill 2 stages
    issue_stage(tiles, 0, 0, gA, gB, tid); CP_COMMIT();
    issue_stage(tiles, 1, 1, gA, gB, tid); CP_COMMIT();

    float acc[4][4][4] = {};

    // per-thread ldmatrix address components
    const int aRowB = wm * 64 + (lane & 15);                        // + i*16
    const int aChB  = lane >> 4;                                    // + 2*kk
    const int bRowB = wn * 32 + (lane & 7) + ((lane >> 4) << 3);    // + jp*16
    const int bChB  = (lane >> 3) & 1;                              // + 2*kk
    const int swz   = lane & 7;
    const int kkOff = (wid & 1) << 1;   // warp-parity kk stagger: 0 or 2

    #pragma unroll 1
    for (int kt = 0; kt < KITERS; ++kt) {
        CP_WAIT1();              // stage kt has landed (<=1 group outstanding)
        __syncthreads();         // all warps done reading stage kt-1
        if (kt + 2 < KITERS)
            issue_stage(tiles, (kt + 2) % 3, kt + 2, gA, gB, tid);
        CP_COMMIT();             // commit every iter (possibly empty group)

        const int s = kt % 3;
        const uint32_t aSt = tiles + (uint32_t)s * STAGE_BYTES;
        const uint32_t bSt = aSt + A_BYTES;

        #pragma unroll
        for (int kkq = 0; kkq < 4; ++kkq) {      // 4 x k16 per 64-elt chunk
            const int kk = (kkq + kkOff) & 3;    // stagger order by warp parity

            uint32_t bf[2][4];
            #pragma unroll
            for (int jp = 0; jp < 2; ++jp) {
                const uint32_t addr = bSt
                    + (uint32_t)((bRowB + jp * 16) * 128)
                    + (uint32_t)((((kk * 2 + bChB) ^ swz) * 16));
                LDSM4(bf[jp][0], bf[jp][1], bf[jp][2], bf[jp][3], addr);
            }

            // A-fragment double buffer: LDSM for subtile i+1 issues between
            // the MMAs of subtile i (hides the ~29cyc LDS latency).
            uint32_t af[2][4];
            {
                const uint32_t addr = aSt
                    + (uint32_t)(aRowB * 128)
                    + (uint32_t)((((kk * 2 + aChB) ^ swz) * 16));
                LDSM4(af[0][0], af[0][1], af[0][2], af[0][3], addr);
            }
            #pragma unroll
            for (int i = 0; i < 4; ++i) {
                if (i < 3) {
                    const uint32_t addr = aSt
                        + (uint32_t)((aRowB + (i + 1) * 16) * 128)
                        + (uint32_t)((((kk * 2 + aChB) ^ swz) * 16));
                    LDSM4(af[(i + 1) & 1][0], af[(i + 1) & 1][1],
                          af[(i + 1) & 1][2], af[(i + 1) & 1][3], addr);
                }
                #pragma unroll
                for (int j = 0; j < 4; ++j)
                    MMA16816(acc[i][j], af[i & 1],
                             bf[j >> 1][(j & 1) * 2],
                             bf[j >> 1][(j & 1) * 2 + 1]);
            }
        }
    }

    // ---------------- epilogue: transform + store ----------------
    const int rBase = wm * 64 + (lane >> 2);        // + i*16 (+8)
    const int cBase = wn * 32 + (lane & 3) * 2;     // + j*8

    #pragma unroll
    for (int i = 0; i < 4; ++i) {
        const int ra = rBase + i * 16;
        const int rb = ra + 8;
        const float xsa = sXs[ra], Ana = sAn[ra];
        const float xsb = sXs[rb], Anb = sAn[rb];
        float* outA = out + (size_t)(m0 + ra) * V_DIM + v0;
        float* outB = out + (size_t)(m0 + rb) * V_DIM + v0;
        #pragma unroll
        for (int j = 0; j < 4; ++j) {
            const int lc = cBase + j * 8;
            const float ys0 = sYsq[lc],     By0 = sBy[lc];
            const float ys1 = sYsq[lc + 1], By1 = sBy[lc + 1];
            float2 pa, pb;
            pa.x = hyp(acc[i][j][0], xsa, Ana, ys0, By0);
            pa.y = hyp(acc[i][j][1], xsa, Ana, ys1, By1);
            pb.x = hyp(acc[i][j][2], xsb, Anb, ys0, By0);
            pb.y = hyp(acc[i][j][3], xsb, Anb, ys1, By1);
            *reinterpret_cast<float2*>(outA + lc) = pa;
            *reinterpret_cast<float2*>(outB + lc) = pb;
        }
    }
}

// ============================================================================
// Launch
// ============================================================================
extern "C" void kernel_launch(void* const* d_in, const int* in_sizes, int n_in,
                              void* d_out, int out_size) {
    const float* hidden = (const float*)d_in[0];
    const float* weight = (const float*)d_in[1];
    float* out = (float*)d_out;

    prep_all<<<PREP_GRID, 256>>>(hidden, weight);

    cudaFuncSetAttribute(hyper_gemm,
                         cudaFuncAttributeMaxDynamicSharedMemorySize, SMEM_DYN);
    dim3 grid(N_TOK / BM, V_DIM / BN);   // m-fastest: A L2-resident, B streamed once
    hyper_gemm<<<grid, THREADS, SMEM_DYN>>>(out);
}